// round 17
// baseline (speedup 1.0000x reference)
#include <cuda_runtime.h>
#include <cuda_fp16.h>
#include <cstdint>

// ---------------------------------------------------------------------------
// MHA block, all fp16 mma.sync (error-budgeted) + R16 coalesced epilogues.
// R17: __launch_bounds__(256,3) on the four hot kernels -> 3 CTAs/SM
// (occupancy 24%->36%, pv wave count 1.73->1.15).
// ---------------------------------------------------------------------------

using f16 = __half;
typedef unsigned int u32;
typedef unsigned long long u64;

namespace {
constexpr int B = 4, S = 2048, D = 512, H = 8, BH = 32, MTOK = 8192;
constexpr long long OUT_ELEMS  = (long long)MTOK * D;
constexpr long long ATTN_ELEMS = (long long)BH * S * (long long)S;

constexpr int TILE = 10240;                       // 128 x 80B
constexpr int G_BUF = 2 * TILE, SM_G = 2 * G_BUF;
constexpr int SM_SC = 4 * TILE;                   // P stage (128x272) overlays
constexpr int PV_P0 = 0, PV_P1 = 18432, PV_V0 = 36864, PV_V1 = 46080,
              PV_RI = 55296, SM_PV = 55808;
}

// ---- device scratch ----------------------------------------------------------
__device__ f16   g_Wt[4][(size_t)D * D];
__device__ f16   g_Xh[3][(size_t)MTOK * D];
__device__ f16   g_Qh[(size_t)MTOK * D];
__device__ f16   g_Kh[(size_t)MTOK * D];
__device__ f16   g_Vh[(size_t)MTOK * D];
__device__ f16   g_Oh[(size_t)MTOK * D];
__device__ f16   g_Ph[(size_t)BH * S * (size_t)S];
__device__ float g_Y[(size_t)MTOK * D];
__device__ float g_rowsum[BH * S];
__device__ float g_attn_fb[(size_t)BH * S * (size_t)S];

// ---- PTX helpers ---------------------------------------------------------------
__device__ __forceinline__ u32 cvta_smem(const void* p) {
    u32 a;
    asm("{ .reg .u64 t; cvta.to.shared.u64 t, %1; cvt.u32.u64 %0, t; }"
        : "=r"(a) : "l"(p));
    return a;
}
__device__ __forceinline__ void ldsm4(u32& r0, u32& r1, u32& r2, u32& r3, u32 a) {
    asm volatile("ldmatrix.sync.aligned.m8n8.x4.shared.b16 {%0,%1,%2,%3}, [%4];"
                 : "=r"(r0), "=r"(r1), "=r"(r2), "=r"(r3) : "r"(a));
}
__device__ __forceinline__ void ldsm2(u32& r0, u32& r1, u32 a) {
    asm volatile("ldmatrix.sync.aligned.m8n8.x2.shared.b16 {%0,%1}, [%2];"
                 : "=r"(r0), "=r"(r1) : "r"(a));
}
__device__ __forceinline__ void ldsm2t(u32& r0, u32& r1, u32 a) {
    asm volatile("ldmatrix.sync.aligned.m8n8.x2.trans.shared.b16 {%0,%1}, [%2];"
                 : "=r"(r0), "=r"(r1) : "r"(a));
}
__device__ __forceinline__ void mma_ff(float* c, const u32* a, const u32* b) {
    asm volatile(
        "mma.sync.aligned.m16n8k16.row.col.f32.f16.f16.f32 "
        "{%0,%1,%2,%3}, {%4,%5,%6,%7}, {%8,%9}, {%0,%1,%2,%3};"
        : "+f"(c[0]), "+f"(c[1]), "+f"(c[2]), "+f"(c[3])
        : "r"(a[0]), "r"(a[1]), "r"(a[2]), "r"(a[3]), "r"(b[0]), "r"(b[1]));
}
__device__ __forceinline__ void cp16(u32 dst, const void* src) {
    asm volatile("cp.async.cg.shared.global [%0], [%1], 16;" :: "r"(dst), "l"(src));
}
__device__ __forceinline__ void cp_commit() {
    asm volatile("cp.async.commit_group;" ::: "memory");
}
__device__ __forceinline__ void cp_wait0() {
    asm volatile("cp.async.wait_group 0;" ::: "memory");
}
__device__ __forceinline__ void cp_wait1() {
    asm volatile("cp.async.wait_group 1;" ::: "memory");
}
__device__ __forceinline__ u32 pack2h(f16 a, f16 b) {
    return (u32)__half_as_ushort(a) | ((u32)__half_as_ushort(b) << 16);
}

// ---------------------------------------------------------------------------
// Prep
// ---------------------------------------------------------------------------
__global__ void whalf_k(const float* __restrict__ w0, const float* __restrict__ w1,
                        const float* __restrict__ w2, const float* __restrict__ w3,
                        f16* __restrict__ o) {
    const float* w = (blockIdx.z == 0) ? w0 : (blockIdx.z == 1) ? w1
                   : (blockIdx.z == 2) ? w2 : w3;
    f16* t = o + (size_t)blockIdx.z * D * D;
    int i = blockIdx.x * 256 + threadIdx.x;
    int k = i >> 9, n = i & 511;
    t[(size_t)n * 512 + k] = __float2half(w[i]);
}
__global__ void xhalf_k(const float* __restrict__ x0, const float* __restrict__ x1,
                        const float* __restrict__ x2, f16* __restrict__ o) {
    const float* x = (blockIdx.z == 0) ? x0 : (blockIdx.z == 1) ? x1 : x2;
    f16* t = o + (size_t)blockIdx.z * MTOK * D;
    const size_t i = ((size_t)blockIdx.x * 256 + threadIdx.x) * 4;
    float4 v = *(const float4*)(x + i);
    *(uint2*)(t + i) = make_uint2(pack2h(__float2half(v.x), __float2half(v.y)),
                                  pack2h(__float2half(v.z), __float2half(v.w)));
}

// ---------------------------------------------------------------------------
// One BK=32 fp16 stage, warp tile 64x32  (A at sbuf, B at sbuf+TILE)
// ---------------------------------------------------------------------------
__device__ __forceinline__ void compute_ff44(float acc[4][4][4], u32 sbuf,
                                             int m0w, int n0w, int lane)
{
    const int la15 = lane & 15, lc = lane >> 4;
    const int l7 = lane & 7, lb = (lane >> 3) & 1;
#pragma unroll
    for (int ks = 0; ks < 2; ks++) {
        const u32 ko = (u32)(ks * 32);
        u32 a4[4][4];
#pragma unroll
        for (int mt = 0; mt < 4; mt++) {
            u32 a = sbuf + (u32)((m0w + mt * 16 + la15) * 80) + ko + lc * 16;
            ldsm4(a4[mt][0], a4[mt][1], a4[mt][2], a4[mt][3], a);
        }
        u32 b2[4][2];
#pragma unroll
        for (int nt = 0; nt < 4; nt++) {
            u32 a = sbuf + TILE + (u32)((n0w + nt * 8 + l7) * 80) + ko + lb * 16;
            ldsm2(b2[nt][0], b2[nt][1], a);
        }
#pragma unroll
        for (int mt = 0; mt < 4; mt++)
#pragma unroll
            for (int nt = 0; nt < 4; nt++)
                mma_ff(acc[mt][nt], a4[mt], b2[nt]);
    }
}

// ---------------------------------------------------------------------------
// gemmf3: batched Q/K/V projections
// ---------------------------------------------------------------------------
__global__ __launch_bounds__(256, 3)
void gemmf3_k(const f16* __restrict__ Xh, const f16* __restrict__ Wt,
              f16* __restrict__ C0, f16* __restrict__ C1, f16* __restrict__ C2)
{
    __shared__ __align__(16) char sm[SM_G];
    const f16* A = Xh + (size_t)blockIdx.z * MTOK * D;
    const f16* Bw = Wt + (size_t)blockIdx.z * D * D;
    f16* C = (blockIdx.z == 0) ? C0 : (blockIdx.z == 1) ? C1 : C2;

    const int tid = threadIdx.x, lane = tid & 31, wi = tid >> 5;
    const int m0 = blockIdx.y * 128, n0 = blockIdx.x * 128;
    const int m0w = (wi >> 2) * 64, n0w = (wi & 3) * 32;
    const u32 sb = cvta_smem(sm);
    const int r = tid >> 1, hf = tid & 1;
    const u32 soff = (u32)(r * 80 + hf * 32);

    float acc[4][4][4];
#pragma unroll
    for (int i = 0; i < 4; i++)
#pragma unroll
        for (int j = 0; j < 4; j++)
#pragma unroll
            for (int q = 0; q < 4; q++) acc[i][j][q] = 0.f;

    auto load_stage = [&](int c, u32 sbuf) {
        const size_t ao = (size_t)(m0 + r) * 512 + c * 32 + hf * 16;
        const size_t bo = (size_t)(n0 + r) * 512 + c * 32 + hf * 16;
        cp16(sbuf + soff,             A + ao);
        cp16(sbuf + soff + 16,        A + ao + 8);
        cp16(sbuf + TILE + soff,      Bw + bo);
        cp16(sbuf + TILE + soff + 16, Bw + bo + 8);
    };

    load_stage(0, sb);
    cp_commit();
    for (int c = 0; c < 16; c++) {
        const u32 cur = sb + (u32)((c & 1) * G_BUF);
        if (c + 1 < 16) {
            load_stage(c + 1, sb + (u32)(((c + 1) & 1) * G_BUF));
            cp_commit();
            cp_wait1();
        } else {
            cp_wait0();
        }
        __syncthreads();
        compute_ff44(acc, cur, m0w, n0w, lane);
        __syncthreads();
    }

    const int g = lane >> 2, tg = lane & 3;
#pragma unroll
    for (int mt = 0; mt < 4; mt++)
#pragma unroll
        for (int h2 = 0; h2 < 2; h2++) {
            const size_t m = (size_t)(m0 + m0w + mt * 16 + h2 * 8 + g);
#pragma unroll
            for (int nt = 0; nt < 4; nt++) {
                const int ncol = n0 + n0w + nt * 8 + tg * 2;
                *(u32*)(C + m * 512 + ncol) =
                    pack2h(__float2half(acc[mt][nt][h2 * 2]),
                           __float2half(acc[mt][nt][h2 * 2 + 1]));
            }
        }
}

// ---------------------------------------------------------------------------
// gemmo: out proj + residual -> f32 Y
// ---------------------------------------------------------------------------
__global__ __launch_bounds__(256, 3)
void gemmo_k(const f16* __restrict__ A, const f16* __restrict__ Bw,
             const float* __restrict__ R, float* __restrict__ Yf)
{
    __shared__ __align__(16) char sm[SM_G];
    const int tid = threadIdx.x, lane = tid & 31, wi = tid >> 5;
    const int m0 = blockIdx.y * 128, n0 = blockIdx.x * 128;
    const int m0w = (wi >> 2) * 64, n0w = (wi & 3) * 32;
    const u32 sb = cvta_smem(sm);
    const int r = tid >> 1, hf = tid & 1;
    const u32 soff = (u32)(r * 80 + hf * 32);

    float acc[4][4][4];
#pragma unroll
    for (int i = 0; i < 4; i++)
#pragma unroll
        for (int j = 0; j < 4; j++)
#pragma unroll
            for (int q = 0; q < 4; q++) acc[i][j][q] = 0.f;

    auto load_stage = [&](int c, u32 sbuf) {
        const size_t ao = (size_t)(m0 + r) * 512 + c * 32 + hf * 16;
        const size_t bo = (size_t)(n0 + r) * 512 + c * 32 + hf * 16;
        cp16(sbuf + soff,             A + ao);
        cp16(sbuf + soff + 16,        A + ao + 8);
        cp16(sbuf + TILE + soff,      Bw + bo);
        cp16(sbuf + TILE + soff + 16, Bw + bo + 8);
    };

    load_stage(0, sb);
    cp_commit();
    for (int c = 0; c < 16; c++) {
        const u32 cur = sb + (u32)((c & 1) * G_BUF);
        if (c + 1 < 16) {
            load_stage(c + 1, sb + (u32)(((c + 1) & 1) * G_BUF));
            cp_commit();
            cp_wait1();
        } else {
            cp_wait0();
        }
        __syncthreads();
        compute_ff44(acc, cur, m0w, n0w, lane);
        __syncthreads();
    }

    const int g = lane >> 2, tg = lane & 3;
#pragma unroll
    for (int mt = 0; mt < 4; mt++)
#pragma unroll
        for (int h2 = 0; h2 < 2; h2++) {
            const size_t m = (size_t)(m0 + m0w + mt * 16 + h2 * 8 + g);
#pragma unroll
            for (int nt = 0; nt < 4; nt++) {
                const int ncol = n0 + n0w + nt * 8 + tg * 2;
                const float2 rv = *(const float2*)(R + m * 512 + ncol);
                *(float2*)(Yf + m * 512 + ncol) =
                    make_float2(acc[mt][nt][h2 * 2] + rv.x,
                                acc[mt][nt][h2 * 2 + 1] + rv.y);
            }
        }
}

// ---------------------------------------------------------------------------
// Scores: cp.async chunks; exp-only fragments -> smem; coalesced
// mask/rowsum/P-store write phase.
// ---------------------------------------------------------------------------
__global__ __launch_bounds__(256, 3)
void scores_k(const f16* __restrict__ Qh, const f16* __restrict__ Kh,
              const unsigned char* __restrict__ mask,
              f16* __restrict__ Ph, float* __restrict__ rowsum)
{
    __shared__ __align__(16) char sm[SM_SC];
    const int tid = threadIdx.x, lane = tid & 31, wi = tid >> 5;
    const int bh = blockIdx.z, b_ = bh >> 3, h_ = bh & 7;
    const int q0 = blockIdx.y * 128, kt0 = blockIdx.x * 128;
    const int m0w = (wi >> 2) * 64, n0w = (wi & 3) * 32;
    const u32 sb = cvta_smem(sm);
    const int r = tid >> 1, hf = tid & 1;
    const u32 soff = (u32)(r * 80 + hf * 32);

#pragma unroll
    for (int c = 0; c < 2; c++) {
        const int k0 = h_ * 64 + c * 32;
        const f16* qa = Qh + (size_t)(b_ * S + q0 + r) * 512 + k0 + hf * 16;
        const f16* ka = Kh + (size_t)(b_ * S + kt0 + r) * 512 + k0 + hf * 16;
        const u32 base = sb + (u32)(c * 2 * TILE);
        cp16(base + soff,             qa);
        cp16(base + soff + 16,        qa + 8);
        cp16(base + TILE + soff,      ka);
        cp16(base + TILE + soff + 16, ka + 8);
        cp_commit();
    }

    float acc[4][4][4];
#pragma unroll
    for (int i = 0; i < 4; i++)
#pragma unroll
        for (int j = 0; j < 4; j++)
#pragma unroll
            for (int q = 0; q < 4; q++) acc[i][j][q] = 0.f;

    cp_wait1();
    __syncthreads();
    compute_ff44(acc, sb, m0w, n0w, lane);
    cp_wait0();
    __syncthreads();
    compute_ff44(acc, sb + 2 * TILE, m0w, n0w, lane);
    __syncthreads();

    // stage exp fragments (pitch 272; conflict-free)
    const int g = lane >> 2, tg = lane & 3;
#pragma unroll
    for (int mt = 0; mt < 4; mt++)
#pragma unroll
        for (int h2 = 0; h2 < 2; h2++) {
            const int srow = m0w + mt * 16 + h2 * 8 + g;
#pragma unroll
            for (int nt = 0; nt < 4; nt++) {
                const int col = n0w + nt * 8 + tg * 2;
                const float e0 = __expf(acc[mt][nt][h2 * 2]     * 0.125f);
                const float e1 = __expf(acc[mt][nt][h2 * 2 + 1] * 0.125f);
                *(u32*)(sm + srow * 272 + col * 2) =
                    pack2h(__float2half(e0), __float2half(e1));
            }
        }
    __syncthreads();

    // coalesced write: mask u64 + rowsum + P store, 16 lanes/row
    const int orow = tid >> 4, l16 = tid & 15;
#pragma unroll
    for (int p = 0; p < 8; p++) {
        const int row = orow + p * 16;
        uint4 v = *(const uint4*)(sm + row * 272 + l16 * 16);
        const u64 mv = *(const u64*)(mask + (size_t)(b_ * S + q0 + row) * S
                                          + kt0 + l16 * 8);
        u32 w[4] = {v.x, v.y, v.z, v.w};
        float rs = 0.f;
#pragma unroll
        for (int e = 0; e < 4; e++) {
            if ((mv >> (16 * e)) & 0xffULL) w[e] &= 0xffff0000u;
            else rs += __half2float(__ushort_as_half((unsigned short)(w[e] & 0xffff)));
            if ((mv >> (16 * e + 8)) & 0xffULL) w[e] &= 0x0000ffffu;
            else rs += __half2float(__ushort_as_half((unsigned short)(w[e] >> 16)));
        }
        *(uint4*)(Ph + ((size_t)bh * S + q0 + row) * S + kt0 + l16 * 8) =
            make_uint4(w[0], w[1], w[2], w[3]);
#pragma unroll
        for (int off = 8; off > 0; off >>= 1)
            rs += __shfl_xor_sync(0xffffffffu, rs, off);
        if (l16 == 0) atomicAdd(&rowsum[(size_t)bh * S + q0 + row], rs);
    }
}

// ---------------------------------------------------------------------------
// PV: O = rinv * (P_unnorm @ V); normalized f32 attn written coalesced.
// ---------------------------------------------------------------------------
__global__ __launch_bounds__(256, 3)
void pv_k(const f16* __restrict__ Ph, const f16* __restrict__ Vh,
          const float* __restrict__ rowsum, float* __restrict__ attn,
          f16* __restrict__ Oh)
{
    extern __shared__ __align__(16) char sm[];
    const int tid = threadIdx.x, lane = tid & 31, wi = tid >> 5;
    const int bh = blockIdx.y, b_ = bh >> 3, h_ = bh & 7;
    const int q0 = blockIdx.x * 128;
    const int m0w = (wi >> 1) * 32, n0w = (wi & 1) * 32;
    const u32 sb = cvta_smem(sm);
    float* rinv_s = (float*)(sm + PV_RI);
    if (tid < 128) rinv_s[tid] = 1.0f / rowsum[(size_t)bh * S + q0 + tid];
    __syncthreads();

    const int r = tid >> 1, hf = tid & 1;
    const int vr = tid >> 3, vs = tid & 7;
    const int la15 = lane & 15, lc = lane >> 4;
    const u32 pbu[2] = {sb + PV_P0, sb + PV_P1};
    const u32 vbu[2] = {sb + PV_V0, sb + PV_V1};
    char* const pbc[2] = {sm + PV_P0, sm + PV_P1};
    const f16* Prow = Ph + ((size_t)bh * S + q0 + r) * S;

    float acc[2][4][4];
#pragma unroll
    for (int i = 0; i < 2; i++)
#pragma unroll
        for (int j = 0; j < 4; j++)
#pragma unroll
            for (int q = 0; q < 4; q++) acc[i][j][q] = 0.f;

    auto load_stage = [&](int c, int buf) {
        const int kt = c * 64;
#pragma unroll
        for (int j = 0; j < 4; j++)
            cp16(pbu[buf] + (u32)(r * 144 + hf * 64 + j * 16),
                 Prow + kt + hf * 32 + j * 8);
#pragma unroll
        for (int j = 0; j < 2; j++) {
            const int row = vr + j * 32;
            cp16(vbu[buf] + (u32)(row * 144 + vs * 16),
                 Vh + (size_t)(b_ * S + kt + row) * 512 + h_ * 64 + vs * 8);
        }
    };

    load_stage(0, 0);
    cp_commit();
    for (int c = 0; c < 32; c++) {
        const int cur = c & 1;
        if (c + 1 < 32) {
            load_stage(c + 1, cur ^ 1);
            cp_commit();
            cp_wait1();
        } else {
            cp_wait0();
        }
        __syncthreads();
#pragma unroll
        for (int ks = 0; ks < 4; ks++) {
            u32 a4[2][4];
#pragma unroll
            for (int mt = 0; mt < 2; mt++) {
                u32 a = pbu[cur] + (u32)((m0w + mt * 16 + la15) * 144 + ks * 32 + lc * 16);
                ldsm4(a4[mt][0], a4[mt][1], a4[mt][2], a4[mt][3], a);
            }
            u32 b2[4][2];
#pragma unroll
            for (int nt = 0; nt < 4; nt++) {
                u32 a = vbu[cur] + (u32)((ks * 16 + la15) * 144 + (n0w + nt * 8) * 2);
                ldsm2t(b2[nt][0], b2[nt][1], a);
            }
#pragma unroll
            for (int mt = 0; mt < 2; mt++)
#pragma unroll
                for (int nt = 0; nt < 4; nt++)
                    mma_ff(acc[mt][nt], a4[mt], b2[nt]);
        }
        // normalized attn write, coalesced: 8 lanes x 32B per 256B row
        {
            const int kt = c * 64;
            const int r32 = tid >> 3, c8 = tid & 7;
#pragma unroll
            for (int p = 0; p < 4; p++) {
                const int row = r32 + p * 32;
                const float rr = rinv_s[row];
                const uint4 w4 = *(const uint4*)(pbc[cur] + row * 144 + c8 * 16);
                const u32 w[4] = {w4.x, w4.y, w4.z, w4.w};
                float o[8];
#pragma unroll
                for (int e = 0; e < 4; e++) {
                    o[2 * e]     = __half2float(__ushort_as_half((unsigned short)(w[e] & 0xffff))) * rr;
                    o[2 * e + 1] = __half2float(__ushort_as_half((unsigned short)(w[e] >> 16))) * rr;
                }
                float* dst = attn + ((size_t)bh * S + q0 + row) * S + kt + c8 * 8;
                *(float4*)dst       = make_float4(o[0], o[1], o[2], o[3]);
                *(float4*)(dst + 4) = make_float4(o[4], o[5], o[6], o[7]);
            }
        }
        __syncthreads();
    }

    const int g = lane >> 2, tg = lane & 3;
#pragma unroll
    for (int mt = 0; mt < 2; mt++)
#pragma unroll
        for (int h2 = 0; h2 < 2; h2++) {
            const int row = m0w + mt * 16 + h2 * 8 + g;
            const float rr = rinv_s[row];
            const size_t m = (size_t)(b_ * S + q0 + row);
#pragma unroll
            for (int nt = 0; nt < 4; nt++) {
                const int ncol = h_ * 64 + n0w + nt * 8 + tg * 2;
                *(u32*)(Oh + m * 512 + ncol) =
                    pack2h(__float2half(acc[mt][nt][h2 * 2] * rr),
                           __float2half(acc[mt][nt][h2 * 2 + 1] * rr));
            }
        }
}

// ---------------------------------------------------------------------------
// Row LayerNorm
// ---------------------------------------------------------------------------
__global__ __launch_bounds__(128)
void ln_k(const float* __restrict__ X, const float* __restrict__ gam,
          const float* __restrict__ bet, float* __restrict__ out)
{
    __shared__ float red[4];
    const int row = blockIdx.x, tid = threadIdx.x;
    const int lane = tid & 31, wid = tid >> 5;
    const float4 x = *(const float4*)(X + (size_t)row * D + tid * 4);

    float s = x.x + x.y + x.z + x.w;
#pragma unroll
    for (int off = 16; off > 0; off >>= 1) s += __shfl_xor_sync(~0u, s, off);
    if (lane == 0) red[wid] = s;
    __syncthreads();
    const float mu = (red[0] + red[1] + red[2] + red[3]) * (1.0f / D);
    __syncthreads();

    const float4 dx = make_float4(x.x - mu, x.y - mu, x.z - mu, x.w - mu);
    float q = dx.x * dx.x + dx.y * dx.y + dx.z * dx.z + dx.w * dx.w;
#pragma unroll
    for (int off = 16; off > 0; off >>= 1) q += __shfl_xor_sync(~0u, q, off);
    if (lane == 0) red[wid] = q;
    __syncthreads();
    const float var = (red[0] + red[1] + red[2] + red[3]) * (1.0f / D);
    const float inv = rsqrtf(var + 1e-5f);

    const float4 g  = *(const float4*)(gam + tid * 4);
    const float4 bb = *(const float4*)(bet + tid * 4);
    float4 y;
    y.x = dx.x * inv * g.x + bb.x;
    y.y = dx.y * inv * g.y + bb.y;
    y.z = dx.z * inv * g.z + bb.z;
    y.w = dx.w * inv * g.w + bb.w;
    *(float4*)(out + (size_t)row * D + tid * 4) = y;
}

// ---------------------------------------------------------------------------
extern "C" void kernel_launch(void* const* d_in, const int* in_sizes, int n_in,
                              void* d_out, int out_size)
{
    (void)in_sizes; (void)n_in;
    const float* Xq = (const float*)d_in[0];
    const float* Xk = (const float*)d_in[1];
    const float* Xv = (const float*)d_in[2];
    const unsigned char* mask = (const unsigned char*)d_in[3];
    const float* Wq = (const float*)d_in[4];
    const float* Wk = (const float*)d_in[5];
    const float* Wv = (const float*)d_in[6];
    const float* Wo = (const float*)d_in[7];
    const float* gam = (const float*)d_in[8];
    const float* bet = (const float*)d_in[9];
    float* out = (float*)d_out;

    f16 *gWt, *gXh, *gQh, *gKh, *gVh, *gOh, *gPh;
    float *gY, *grs, *gfb;
    cudaGetSymbolAddress((void**)&gWt, g_Wt);
    cudaGetSymbolAddress((void**)&gXh, g_Xh);
    cudaGetSymbolAddress((void**)&gQh, g_Qh);
    cudaGetSymbolAddress((void**)&gKh, g_Kh);
    cudaGetSymbolAddress((void**)&gVh, g_Vh);
    cudaGetSymbolAddress((void**)&gOh, g_Oh);
    cudaGetSymbolAddress((void**)&gPh, g_Ph);
    cudaGetSymbolAddress((void**)&gY, g_Y);
    cudaGetSymbolAddress((void**)&grs, g_rowsum);
    cudaGetSymbolAddress((void**)&gfb, g_attn_fb);
    const size_t DD = (size_t)D * D;

    cudaFuncSetAttribute(pv_k, cudaFuncAttributeMaxDynamicSharedMemorySize, SM_PV);

    float* attnp = ((long long)out_size >= OUT_ELEMS + ATTN_ELEMS)
                       ? (out + OUT_ELEMS) : gfb;

    // 1) prep
    whalf_k<<<dim3(1024, 1, 4), 256>>>(Wq, Wk, Wv, Wo, gWt);
    xhalf_k<<<dim3(4096, 1, 3), 256>>>(Xq, Xk, Xv, gXh);
    cudaMemsetAsync(grs, 0, sizeof(float) * BH * S);

    // 2) projections (Q,K,V batched)
    gemmf3_k<<<dim3(4, 64, 3), 256>>>(gXh, gWt, gQh, gKh, gVh);

    // 3) scores -> unnormalized fp16 P + rowsums
    scores_k<<<dim3(16, 16, 32), 256>>>(gQh, gKh, mask, gPh, grs);

    // 4) PV + normalized attn write
    pv_k<<<dim3(16, 32), 256, SM_PV>>>(gPh, gVh, grs, attnp, gOh);

    // 5) out proj + residual, then LayerNorm
    gemmo_k<<<dim3(4, 64), 256>>>(gOh, gWt + 3 * DD, Xq, gY);
    ln_k<<<MTOK, 128>>>(gY, gam, bet, out);
}